// round 8
// baseline (speedup 1.0000x reference)
#include <cuda_runtime.h>
#include <math.h>
#include <stdint.h>

// ---------------- problem constants ----------------
#define BB    64
#define NBLK  128     // 32 row-groups (rg) x 4 k-groups (kg)
#define NTHR  512
#define WST2  260     // SMEM W row stride (256 + 4 pad)
#define ATTN_THRESH 1e-10f

// ---------------- SMEM layout (float offsets) ----------------
#define OFF_W     0        // 64 rows x 260        = 16640
#define OFF_A     16640    // A slice k-pair layout = 16384 (128 kp x 64 b x 2)
#define OFF_GST   33024    // gates/partial stage   = 4096
#define OFF_ATTNA 37120    // 1024
#define OFF_ATTNB 38144    // 1024
#define OFF_C     39168    // 1024 (owner c-state, [jl][b])
#define OFF_H2    40192    // 1024
#define OFF_BS    41216    // 64  (bias per local row)
#define OFF_WSP   41280    // 32  (W_sp slice, [g][jl])
#define OFF_BSP   41312    // 2
#define OFF_SCR   41316    // 32
#define OFF_WIN   41348    // 2 ints
#define SMEM_FLOATS 41352
#define SMEM_BYTES  (SMEM_FLOATS*4)

// ---------------- persistent global state ----------------
// g_AT2: k-pair interleaved activations: (k,b) at (k>>1)*128 + b*2 + (k&1)
// k<512 = time_in rows, k>=512 = h rows.
__device__ __align__(16) float g_AT2[1024 * BB];
__device__ __align__(16) float g_part[3 * 32 * 4096];  // [kg-1][rg][row*64+b]
__device__ float    g_spp[BB * 64];                    // [b][g*32+rg]
__device__ unsigned g_cnt;
__device__ unsigned g_gen;

// ---------------- f32x2 helpers ----------------
__device__ __forceinline__ void fma2(unsigned long long &d,
                                     unsigned long long a, unsigned long long b) {
    asm("fma.rn.f32x2 %0, %1, %2, %0;" : "+l"(d) : "l"(a), "l"(b));
}
__device__ __forceinline__ void split2(float4 w, unsigned long long &lo,
                                       unsigned long long &hi) {
    asm("mov.b64 %0, {%2, %3};\n\tmov.b64 %1, {%4, %5};"
        : "=l"(lo), "=l"(hi) : "f"(w.x), "f"(w.y), "f"(w.z), "f"(w.w));
}
__device__ __forceinline__ float hsum2(unsigned long long v) {
    float lo, hi;
    asm("mov.b64 {%0, %1}, %2;" : "=f"(lo), "=f"(hi) : "l"(v));
    return lo + hi;
}

// ---------------- grid-wide barrier ----------------
__device__ __forceinline__ void grid_barrier() {
    __syncthreads();
    __threadfence();
    if (threadIdx.x == 0) {
        unsigned gen = *(volatile unsigned*)&g_gen;
        if (atomicAdd(&g_cnt, 1u) == gridDim.x - 1) {
            atomicExch(&g_cnt, 0u);
            __threadfence();
            atomicExch(&g_gen, gen + 1u);
        } else {
            while (*(volatile unsigned*)&g_gen == gen) { __nanosleep(32); }
        }
    }
    __syncthreads();
    __threadfence();
}

// ---------------- block reductions (512 thr = 16 warps) ----------------
__device__ __forceinline__ float brsum(float v, float* scr) {
#pragma unroll
    for (int o = 16; o; o >>= 1) v += __shfl_xor_sync(0xffffffffu, v, o);
    __syncthreads();
    if ((threadIdx.x & 31) == 0) scr[threadIdx.x >> 5] = v;
    __syncthreads();
    if (threadIdx.x < 32) {
        float w = (threadIdx.x < 16) ? scr[threadIdx.x] : 0.f;
#pragma unroll
        for (int o = 8; o; o >>= 1) w += __shfl_xor_sync(0xffffffffu, w, o);
        if (threadIdx.x == 0) scr[0] = w;
    }
    __syncthreads();
    return scr[0];
}
__device__ __forceinline__ float brmax(float v, float* scr) {
#pragma unroll
    for (int o = 16; o; o >>= 1) v = fmaxf(v, __shfl_xor_sync(0xffffffffu, v, o));
    __syncthreads();
    if ((threadIdx.x & 31) == 0) scr[threadIdx.x >> 5] = v;
    __syncthreads();
    if (threadIdx.x < 32) {
        float w = (threadIdx.x < 16) ? scr[threadIdx.x] : 0.f;
#pragma unroll
        for (int o = 8; o; o >>= 1) w = fmaxf(w, __shfl_xor_sync(0xffffffffu, w, o));
        if (threadIdx.x == 0) scr[0] = w;
    }
    __syncthreads();
    return scr[0];
}

// ---------------- time_in over attn window ----------------
__device__ __forceinline__ void compute_tin(const float* __restrict__ input,
                                            const float* __restrict__ an,
                                            float* tinred, int b, int dstart,
                                            int lo, int hi, int tid) {
    __syncthreads();
    const int dloc = tid & 255;
    const int ls   = tid >> 8;       // 0..1
    float s = 0.f;
    const float* xp = input + (size_t)b * 512 + dstart + dloc;
    for (int l = lo + ls; l <= hi; l += 2)
        s = fmaf(xp[(size_t)l * 32768], an[l], s);
    tinred[ls * 256 + dloc] = s;
    __syncthreads();
    if (tid < 256) {
        float v = tinred[tid] + tinred[256 + tid];
        const int k = dstart + tid;
        g_AT2[(k >> 1) * 128 + b * 2 + (k & 1)] = v;
    }
}

// ---------------- persistent kernel ----------------
__global__ void __launch_bounds__(NTHR, 1)
spacing_rnn_kernel(const float* __restrict__ input, const int* __restrict__ plen,
                   const float* __restrict__ Wih, const float* __restrict__ Whh,
                   const float* __restrict__ bih, const float* __restrict__ bhh,
                   const float* __restrict__ Wsp, const float* __restrict__ bsp,
                   float* __restrict__ out, int L)
{
    extern __shared__ float sm[];
    float* Wsm   = sm + OFF_W;
    float* Asm   = sm + OFF_A;
    float* gst   = sm + OFF_GST;
    float* attnA = sm + OFF_ATTNA;
    float* attnB = sm + OFF_ATTNB;
    float* csm   = sm + OFF_C;
    float* h2s   = sm + OFF_H2;
    float* bsum  = sm + OFF_BS;
    float* wspc  = sm + OFF_WSP;
    float* bspc  = sm + OFF_BSP;
    float* scr   = sm + OFF_SCR;
    int*   win   = (int*)(sm + OFF_WIN);

    const int tid = threadIdx.x;
    const int bi  = blockIdx.x;
    const int RG  = bi & 31;          // row-group: hidden dims [RG*16, RG*16+16)
    const int KG  = bi >> 5;          // k-group:   k in [KG*256, KG*256+256)
    const int b      = bi & 63;       // phase-B batch served by this block
    const int dstart = (bi >> 6) * 256;
    int len = plen[0];
    if (len <= 0 || len > L) len = L;

    // ---------------- prologue ----------------
    // W slice: local row lr = gate*16 + jl -> global row gr = gate*512 + RG*16 + jl
    {
        const float* Wsrc = (KG < 2) ? Wih : Whh;
        const int koff = (KG & 1) * 256;
        for (int li = tid; li < 64 * 256; li += NTHR) {
            int lr = li >> 8, kl = li & 255;
            int gr = (lr >> 4) * 512 + RG * 16 + (lr & 15);
            Wsm[lr * WST2 + kl] = Wsrc[gr * 512 + koff + kl];
        }
    }
    if (tid < 64) {
        int gr = (tid >> 4) * 512 + RG * 16 + (tid & 15);
        bsum[tid] = bih[gr] + bhh[gr];
    }
    if (tid < 32) wspc[tid] = Wsp[(tid >> 4) * 512 + RG * 16 + (tid & 15)];
    if (tid < 2)  bspc[tid] = bsp[tid];
    attnA[tid] = (tid == 0) ? 1.f : 0.f;
    attnA[tid + 512] = 0.f;
    attnB[tid] = 0.f;
    attnB[tid + 512] = 0.f;
    for (int e = tid; e < 1024; e += NTHR) csm[e] = 0.f;
    if (KG == 0) {   // owners zero h0 in g_AT2
        for (int e = tid; e < 1024; e += NTHR) {
            int jl = e >> 6, bb = e & 63;
            int k = 512 + RG * 16 + jl;
            g_AT2[(k >> 1) * 128 + bb * 2 + (k & 1)] = 0.f;
        }
    }
    __syncthreads();
    compute_tin(input, attnA, gst, b, dstart, 0, 0, tid);   // tin(0) = x[:, :, 0]
    grid_barrier();

    float* cur = attnA;
    float* nxt = attnB;
    int sup = 0;

    for (int t = 0; t < len; t++) {
        // ===== PHASE A: stage A-slice, f32x2 GEMM, partial output =====
        {   // stage 64KB A-slice (unique, coalesced) into SMEM
            const float4* src = (const float4*)(g_AT2 + KG * 16384);
            float4* dst = (float4*)Asm;
            for (int i = tid; i < 4096; i += NTHR) dst[i] = src[i];
        }
        __syncthreads();
        {
            const int bt = tid & 15;              // 16 b-tiles
            const int rt = (tid >> 4) & 15;       // 16 r-tiles
            const int ks = tid >> 8;              // 2 k-halves (128 k each)
            const int b0 = bt * 4, r0 = rt * 4, k0 = ks * 128;
            unsigned long long acc[4][4];
#pragma unroll
            for (int i = 0; i < 4; i++)
#pragma unroll
                for (int j = 0; j < 4; j++) acc[i][j] = 0ull;
            const float* Wb = Wsm + r0 * WST2;
#pragma unroll 4
            for (int kk = 0; kk < 128; kk += 4) {
                const int k = k0 + kk;
                float4 w0f = *(const float4*)(Wb + 0 * WST2 + k);
                float4 w1f = *(const float4*)(Wb + 1 * WST2 + k);
                float4 w2f = *(const float4*)(Wb + 2 * WST2 + k);
                float4 w3f = *(const float4*)(Wb + 3 * WST2 + k);
                const float* pa = Asm + (k >> 1) * 128 + b0 * 2;
                ulonglong2 A01 = *(const ulonglong2*)(pa);
                ulonglong2 A23 = *(const ulonglong2*)(pa + 4);
                ulonglong2 B01 = *(const ulonglong2*)(pa + 128);
                ulonglong2 B23 = *(const ulonglong2*)(pa + 132);
                unsigned long long wl0, wh0, wl1, wh1, wl2, wh2, wl3, wh3;
                split2(w0f, wl0, wh0); split2(w1f, wl1, wh1);
                split2(w2f, wl2, wh2); split2(w3f, wl3, wh3);
                fma2(acc[0][0], A01.x, wl0); fma2(acc[0][1], A01.x, wl1);
                fma2(acc[0][2], A01.x, wl2); fma2(acc[0][3], A01.x, wl3);
                fma2(acc[1][0], A01.y, wl0); fma2(acc[1][1], A01.y, wl1);
                fma2(acc[1][2], A01.y, wl2); fma2(acc[1][3], A01.y, wl3);
                fma2(acc[2][0], A23.x, wl0); fma2(acc[2][1], A23.x, wl1);
                fma2(acc[2][2], A23.x, wl2); fma2(acc[2][3], A23.x, wl3);
                fma2(acc[3][0], A23.y, wl0); fma2(acc[3][1], A23.y, wl1);
                fma2(acc[3][2], A23.y, wl2); fma2(acc[3][3], A23.y, wl3);
                fma2(acc[0][0], B01.x, wh0); fma2(acc[0][1], B01.x, wh1);
                fma2(acc[0][2], B01.x, wh2); fma2(acc[0][3], B01.x, wh3);
                fma2(acc[1][0], B01.y, wh0); fma2(acc[1][1], B01.y, wh1);
                fma2(acc[1][2], B01.y, wh2); fma2(acc[1][3], B01.y, wh3);
                fma2(acc[2][0], B23.x, wh0); fma2(acc[2][1], B23.x, wh1);
                fma2(acc[2][2], B23.x, wh2); fma2(acc[2][3], B23.x, wh3);
                fma2(acc[3][0], B23.y, wh0); fma2(acc[3][1], B23.y, wh1);
                fma2(acc[3][2], B23.y, wh2); fma2(acc[3][3], B23.y, wh3);
            }
            // reduce the two k-halves via gst (tile-major scratch)
            float s[4][4];
#pragma unroll
            for (int i = 0; i < 4; i++)
#pragma unroll
                for (int j = 0; j < 4; j++) s[i][j] = hsum2(acc[i][j]);
            const int tbase = (rt * 16 + bt) * 16;
            if (ks == 1) {
#pragma unroll
                for (int i = 0; i < 4; i++)
#pragma unroll
                    for (int j = 0; j < 4; j++) gst[tbase + i * 4 + j] = s[i][j];
            }
            __syncthreads();
            if (ks == 0) {
#pragma unroll
                for (int i = 0; i < 4; i++)
#pragma unroll
                    for (int j = 0; j < 4; j++) s[i][j] += gst[tbase + i * 4 + j];
            }
            __syncthreads();
            if (ks == 0) {   // write row-major partials: value (b0+i, r0+j) -> [row][b]
#pragma unroll
                for (int i = 0; i < 4; i++)
#pragma unroll
                    for (int j = 0; j < 4; j++) gst[(r0 + j) * 64 + b0 + i] = s[i][j];
            }
        }
        __syncthreads();
        if (KG > 0) {   // export partials (coalesced)
            float4* dst = (float4*)(g_part + (size_t)(KG - 1) * 131072 + RG * 4096);
            const float4* src = (const float4*)gst;
            for (int i = tid; i < 1024; i += NTHR) dst[i] = src[i];
        }
        grid_barrier();   // barrier2: partials visible

        // ===== owner gather + LSTM cell (KG==0 blocks only) =====
        if (KG == 0) {
            {
                float4* g4 = (float4*)gst;
                const float4* p0 = (const float4*)(g_part + (size_t)0 * 131072 + RG * 4096);
                const float4* p1 = (const float4*)(g_part + (size_t)1 * 131072 + RG * 4096);
                const float4* p2 = (const float4*)(g_part + (size_t)2 * 131072 + RG * 4096);
                for (int i = tid; i < 1024; i += NTHR) {
                    float4 a = g4[i], x0 = p0[i], x1 = p1[i], x2 = p2[i];
                    a.x += x0.x + x1.x + x2.x;
                    a.y += x0.y + x1.y + x2.y;
                    a.z += x0.z + x1.z + x2.z;
                    a.w += x0.w + x1.w + x2.w;
                    g4[i] = a;
                }
            }
            __syncthreads();
            for (int e = tid; e < 1024; e += NTHR) {   // cell: e = jl*64 + b
                const int jl = e >> 6, bb = e & 63;
                float gi = gst[(0  + jl) * 64 + bb] + bsum[0  + jl];
                float gf = gst[(16 + jl) * 64 + bb] + bsum[16 + jl];
                float gg = gst[(32 + jl) * 64 + bb] + bsum[32 + jl];
                float go = gst[(48 + jl) * 64 + bb] + bsum[48 + jl];
                float c  = csm[e];
                float si = 1.f / (1.f + __expf(-gi));
                float sf = 1.f / (1.f + __expf(-gf));
                float so = 1.f / (1.f + __expf(-go));
                float c2 = sf * c + si * tanhf(gg);
                float h2 = so * tanhf(c2);
                csm[e] = c2;
                h2s[e] = h2;
                out[(size_t)t * 32768 + (size_t)bb * 512 + RG * 16 + jl] = h2;
                const int k = 512 + RG * 16 + jl;   // publish h
                g_AT2[(k >> 1) * 128 + bb * 2 + (k & 1)] = h2;
            }
            __syncthreads();
            if (tid < 128) {   // sp partial over this block's 16 dims
                const int g = tid >> 6, bb = tid & 63;
                float s2 = 0.f;
#pragma unroll
                for (int jl = 0; jl < 16; jl++)
                    s2 = fmaf(h2s[jl * 64 + bb], wspc[g * 16 + jl], s2);
                g_spp[bb * 64 + g * 32 + RG] = s2;
            }
        }
        grid_barrier();   // barrier3: h + sp partials visible

        // ===== PHASE B: attn update + time_in (all blocks) =====
        if (t + 1 < len) {
            {   // reduce sp over 32 owners for batch b
                float v = (tid < 64) ? g_spp[b * 64 + tid] : 0.f;
#pragma unroll
                for (int o = 16; o; o >>= 1) v += __shfl_xor_sync(0xffffffffu, v, o);
                const int w = tid >> 5;
                if (w < 2 && (tid & 31) == 0) scr[28 + w] = v;
                __syncthreads();
                if (tid == 0) {
                    scr[24] = 1.f / (1.f + __expf(-(scr[28] + bspc[0])));
                    float pp = scr[29] + bspc[1];
                    scr[25] = (pp > 0.f ? pp : 0.f) + 1.f;
                }
                __syncthreads();
            }
            const float shift = scr[24];
            const float p     = scr[25];
            const int sup2 = min(sup + 1, L - 1);
            __syncthreads();
            if (tid == 0) { win[0] = 0x7fffffff; win[1] = -1; }
            const int i1 = tid, i2 = tid + 512;
            float a2a = 0.f, a2b = 0.f;
            if (i1 <= sup2) {
                float a  = cur[i1];
                float ap = (i1 > 0) ? cur[i1 - 1] : 0.f;
                a2a = (1.f - shift) * a + shift * ap;
            }
            if (i2 <= sup2) {
                float a  = cur[i2];
                float ap = cur[i2 - 1];
                a2b = (1.f - shift) * a + shift * ap;
            }
            float amax  = brmax(fmaxf(a2a, a2b), scr);
            float lmax  = __logf(amax);
            float pa2   = (a2a > 0.f) ? __expf(p * (__logf(a2a) - lmax)) : 0.f;
            float pb2   = (a2b > 0.f) ? __expf(p * (__logf(a2b) - lmax)) : 0.f;
            float ssum  = brsum(pa2 + pb2, scr);
            float inv   = 1.f / ssum;
            float na = pa2 * inv, nb = pb2 * inv;
            nxt[i1] = na;
            nxt[i2] = nb;
            if (na >= ATTN_THRESH) { atomicMin(&win[0], i1); atomicMax(&win[1], i1); }
            if (nb >= ATTN_THRESH) { atomicMin(&win[0], i2); atomicMax(&win[1], i2); }
            __syncthreads();
            const int lo = win[0], hi = win[1];
            compute_tin(input, nxt, gst, b, dstart, lo, hi, tid);
            float* tsw = cur; cur = nxt; nxt = tsw;
            sup = sup2;
            grid_barrier();   // barrier1: tin published for next step
        }
    }
}

extern "C" void kernel_launch(void* const* d_in, const int* in_sizes, int n_in,
                              void* d_out, int out_size) {
    const float* input = (const float*)d_in[0];
    const int*   plen  = (const int*)  d_in[1];
    const float* Wih   = (const float*)d_in[2];
    const float* Whh   = (const float*)d_in[3];
    const float* bih   = (const float*)d_in[4];
    const float* bhh   = (const float*)d_in[5];
    const float* Wsp   = (const float*)d_in[6];
    const float* bsp   = (const float*)d_in[7];
    float* out = (float*)d_out;

    int L = in_sizes[0] / (BB * 512);  // 1000

    cudaFuncSetAttribute(spacing_rnn_kernel,
                         cudaFuncAttributeMaxDynamicSharedMemorySize, SMEM_BYTES);
    spacing_rnn_kernel<<<NBLK, NTHR, SMEM_BYTES>>>(input, plen, Wih, Whh, bih, bhh,
                                                   Wsp, bsp, out, L);
}